// round 1
// baseline (speedup 1.0000x reference)
#include <cuda_runtime.h>

// ---------------------------------------------------------------------------
// Net_23905787969856: x[4096,1,28,28] -> conv1(1->32,3x3,SAME)*mask relu
//   -> conv2(32->64,3x3,SAME)*mask relu -> maxpool2x2 -> FC(12544->128) relu
//   -> FC(128->10) -> log_softmax
// Scratch lives in __device__ globals (no allocations allowed).
// ---------------------------------------------------------------------------

#define BATCH 4096
#define HW 784            // 28*28
#define C1 32
#define C2 64
#define POOLHW 196        // 14*14
#define FEAT 12544        // 64*196
#define HID 128

__device__ float g_h1[(size_t)BATCH * HW * C1];   // NHWC [B,28,28,32]  (411 MB)
__device__ float g_h2[(size_t)BATCH * FEAT];      // NCHW flat [B,12544] (205 MB)
__device__ float g_h3[(size_t)BATCH * HID];       // [B,128]

// ---------------------------------------------------------------------------
// Kernel 1: conv1 + bias + mask + relu. One thread per output element (b,pos,c).
// Warp shares (b,pos) -> x window loads are broadcast; stores fully coalesced.
// ---------------------------------------------------------------------------
__global__ void conv1_kernel(const float* __restrict__ x,
                             const float* __restrict__ W1,
                             const float* __restrict__ b1, int B) {
    __shared__ float w1s[C1 * 9];
    __shared__ float b1s[C1];
    int tid = threadIdx.x;
    for (int i = tid; i < C1 * 9; i += blockDim.x) w1s[i] = W1[i];
    if (tid < C1) b1s[tid] = b1[tid];
    __syncthreads();

    int id = blockIdx.x * blockDim.x + tid;
    int total = B * HW * C1;
    if (id >= total) return;
    int c = id & 31;
    int pos = (id >> 5) % HW;
    int b = id / (HW * C1);
    int y = pos / 28, xx = pos % 28;
    const float* xb = x + (size_t)b * HW;

    float cen = xb[pos];
    float acc = b1s[c];
#pragma unroll
    for (int ky = 0; ky < 3; ky++) {
        int iy = y + ky - 1;
        if (iy < 0 || iy >= 28) continue;
#pragma unroll
        for (int kx = 0; kx < 3; kx++) {
            int ix = xx + kx - 1;
            if (ix < 0 || ix >= 28) continue;
            acc += w1s[c * 9 + ky * 3 + kx] * xb[iy * 28 + ix];
        }
    }
    float o = (cen != 0.0f) ? fmaxf(acc, 0.0f) : 0.0f;
    g_h1[(size_t)id] = o;   // id == (b*784+pos)*32 + c  (NHWC)
}

// ---------------------------------------------------------------------------
// Kernel 2: conv2 + bias + mask + relu + 2x2 maxpool, fused.
// One CTA per image. Whole h1 image (zero-padded 30x30, pixel stride 33 for
// bank-conflict-free reads) in smem; loop over 4 output-channel groups of 16.
// Thread = one pooled position (196 active of 224); computes 4 pixels x 16 ch
// in registers (64 accumulators) -> 64 FMA per 20 LDS.
// Writes pooled output in NCHW flatten order: b*12544 + c*196 + pos.
// ---------------------------------------------------------------------------
#define SM_H1 (30 * 30 * 33)   // 29700 floats
#define SM_W2 (16 * 32 * 9)    // 4608 floats
#define CONV2_SMEM ((SM_H1 + SM_W2) * 4)

__global__ __launch_bounds__(224, 1)
void conv2_pool_kernel(const float* __restrict__ x,
                       const float* __restrict__ W2,
                       const float* __restrict__ b2, int B) {
    extern __shared__ float sm[];
    float* h1s = sm;            // [30*30][33] padded image
    float* w2s = sm + SM_H1;    // [(ci*9+k)*16 + c]

    int b = blockIdx.x;
    int tid = threadIdx.x;

    for (int i = tid; i < SM_H1; i += 224) h1s[i] = 0.0f;
    __syncthreads();
    const float* src = g_h1 + (size_t)b * (HW * C1);
    for (int i = tid; i < HW * C1; i += 224) {
        int pix = i >> 5, ci = i & 31;
        int y = pix / 28, xx = pix % 28;
        h1s[((y + 1) * 30 + (xx + 1)) * 33 + ci] = src[i];
    }

    bool m0 = false, m1 = false, m2 = false, m3 = false;
    int oy = 0, ox = 0;
    if (tid < POOLHW) {
        oy = tid / 14; ox = tid % 14;
        const float* xb = x + (size_t)b * HW;
        m0 = xb[(2 * oy) * 28 + 2 * ox] != 0.0f;
        m1 = xb[(2 * oy) * 28 + 2 * ox + 1] != 0.0f;
        m2 = xb[(2 * oy + 1) * 28 + 2 * ox] != 0.0f;
        m3 = xb[(2 * oy + 1) * 28 + 2 * ox + 1] != 0.0f;
    }
    __syncthreads();

    for (int g = 0; g < 4; g++) {
        for (int i = tid; i < SM_W2; i += 224) {
            int c = i & 15;
            int rest = i >> 4;                      // ci*9 + k
            w2s[i] = W2[(g * 16 + c) * 288 + rest];
        }
        __syncthreads();

        if (tid < POOLHW) {
            float a0[16], a1[16], a2[16], a3[16];
#pragma unroll
            for (int c = 0; c < 16; c++) { a0[c] = a1[c] = a2[c] = a3[c] = 0.0f; }

            int r0 = (2 * oy) * 30 + 2 * ox;        // padded coord of top-left pixel
#pragma unroll
            for (int k = 0; k < 9; k++) {
                int base = (r0 + (k / 3) * 30 + (k % 3)) * 33;
#pragma unroll 4
                for (int ci = 0; ci < 32; ci++) {
                    float i00 = h1s[base + ci];
                    float i01 = h1s[base + 33 + ci];
                    float i10 = h1s[base + 990 + ci];
                    float i11 = h1s[base + 990 + 33 + ci];
                    const float* w = &w2s[(ci * 9 + k) * 16];
#pragma unroll
                    for (int c = 0; c < 16; c++) {
                        float wv = w[c];
                        a0[c] += i00 * wv;
                        a1[c] += i01 * wv;
                        a2[c] += i10 * wv;
                        a3[c] += i11 * wv;
                    }
                }
            }
            float* dst = g_h2 + (size_t)b * FEAT + (g * 16) * POOLHW + tid;
#pragma unroll
            for (int c = 0; c < 16; c++) {
                float bb = b2[g * 16 + c];
                float v = 0.0f;
                if (m0) v = fmaxf(v, a0[c] + bb);
                if (m1) v = fmaxf(v, a1[c] + bb);
                if (m2) v = fmaxf(v, a2[c] + bb);
                if (m3) v = fmaxf(v, a3[c] + bb);
                dst[c * POOLHW] = v;
            }
        }
        __syncthreads();
    }
}

// ---------------------------------------------------------------------------
// Kernel 3: FC1 GEMM [4096,12544] x [12544,128] + bias + relu.
// BM=32 BN=128 BK=32, 256 threads, 4x4 register tile. 128 CTAs.
// ---------------------------------------------------------------------------
__global__ __launch_bounds__(256)
void fc1_kernel(const float* __restrict__ Wl1, const float* __restrict__ bl1) {
    __shared__ float As[32][36];   // pad 36 -> float4-aligned row starts
    __shared__ float Bs[32][128];

    int tid = threadIdx.x;
    int rowBase = blockIdx.x * 32;
    int tx = tid % 32, ty = tid / 32;
    int ar = tid / 8, ac4 = tid % 8;

    float acc[4][4] = {};

    for (int k0 = 0; k0 < FEAT; k0 += 32) {
        float4 av = *(const float4*)&g_h2[(size_t)(rowBase + ar) * FEAT + k0 + ac4 * 4];
        *(float4*)&As[ar][ac4 * 4] = av;
#pragma unroll
        for (int i = 0; i < 4; i++) {
            int f = i * 256 + tid;
            int r = f / 32, c4 = f % 32;
            *(float4*)&Bs[r][c4 * 4] = *(const float4*)&Wl1[(size_t)(k0 + r) * HID + c4 * 4];
        }
        __syncthreads();
#pragma unroll
        for (int kk = 0; kk < 32; kk++) {
            float a0 = As[ty * 4 + 0][kk];
            float a1 = As[ty * 4 + 1][kk];
            float a2 = As[ty * 4 + 2][kk];
            float a3 = As[ty * 4 + 3][kk];
            float4 bv = *(const float4*)&Bs[kk][tx * 4];
            acc[0][0] += a0 * bv.x; acc[0][1] += a0 * bv.y; acc[0][2] += a0 * bv.z; acc[0][3] += a0 * bv.w;
            acc[1][0] += a1 * bv.x; acc[1][1] += a1 * bv.y; acc[1][2] += a1 * bv.z; acc[1][3] += a1 * bv.w;
            acc[2][0] += a2 * bv.x; acc[2][1] += a2 * bv.y; acc[2][2] += a2 * bv.z; acc[2][3] += a2 * bv.w;
            acc[3][0] += a3 * bv.x; acc[3][1] += a3 * bv.y; acc[3][2] += a3 * bv.z; acc[3][3] += a3 * bv.w;
        }
        __syncthreads();
    }

    float4 bl = *(const float4*)&bl1[tx * 4];
#pragma unroll
    for (int i = 0; i < 4; i++) {
        int row = rowBase + ty * 4 + i;
        float4 v;
        v.x = fmaxf(acc[i][0] + bl.x, 0.0f);
        v.y = fmaxf(acc[i][1] + bl.y, 0.0f);
        v.z = fmaxf(acc[i][2] + bl.z, 0.0f);
        v.w = fmaxf(acc[i][3] + bl.w, 0.0f);
        *(float4*)&g_h3[(size_t)row * HID + tx * 4] = v;
    }
}

// ---------------------------------------------------------------------------
// Kernel 4: FC2 (128->10) + log_softmax. One warp per row.
// ---------------------------------------------------------------------------
__global__ __launch_bounds__(256)
void fc2_kernel(const float* __restrict__ Wl2, const float* __restrict__ bl2,
                float* __restrict__ out, int B) {
    __shared__ float ws[128 * 10];
    __shared__ float bs[10];
    int tid = threadIdx.x;
    for (int i = tid; i < 1280; i += 256) ws[i] = Wl2[i];
    if (tid < 10) bs[tid] = bl2[tid];
    __syncthreads();

    int w = blockIdx.x * 8 + tid / 32;
    int lane = tid % 32;
    if (w >= B) return;

    const float* h = g_h3 + (size_t)w * HID;
    float acc[10];
#pragma unroll
    for (int j = 0; j < 10; j++) acc[j] = 0.0f;
#pragma unroll
    for (int i = 0; i < 4; i++) {
        int kk = lane + 32 * i;
        float hv = h[kk];
        const float* wr = &ws[kk * 10];
#pragma unroll
        for (int j = 0; j < 10; j++) acc[j] += hv * wr[j];
    }
#pragma unroll
    for (int j = 0; j < 10; j++) {
#pragma unroll
        for (int off = 16; off > 0; off >>= 1)
            acc[j] += __shfl_xor_sync(0xffffffffu, acc[j], off);
    }
    if (lane == 0) {
        float z[10];
        float mx = -1e30f;
#pragma unroll
        for (int j = 0; j < 10; j++) { z[j] = acc[j] + bs[j]; mx = fmaxf(mx, z[j]); }
        float s = 0.0f;
#pragma unroll
        for (int j = 0; j < 10; j++) s += expf(z[j] - mx);
        float l = logf(s);
#pragma unroll
        for (int j = 0; j < 10; j++) out[(size_t)w * 10 + j] = z[j] - mx - l;
    }
}

// ---------------------------------------------------------------------------
extern "C" void kernel_launch(void* const* d_in, const int* in_sizes, int n_in,
                              void* d_out, int out_size) {
    const float* x   = (const float*)d_in[0];
    const float* W1  = (const float*)d_in[1];
    const float* b1  = (const float*)d_in[2];
    const float* W2  = (const float*)d_in[3];
    const float* b2  = (const float*)d_in[4];
    const float* Wl1 = (const float*)d_in[5];
    const float* bl1 = (const float*)d_in[6];
    const float* Wl2 = (const float*)d_in[7];
    const float* bl2 = (const float*)d_in[8];
    float* out = (float*)d_out;

    int B = in_sizes[0] / HW;   // 4096

    int total1 = B * HW * C1;
    conv1_kernel<<<(total1 + 255) / 256, 256>>>(x, W1, b1, B);

    cudaFuncSetAttribute(conv2_pool_kernel,
                         cudaFuncAttributeMaxDynamicSharedMemorySize, CONV2_SMEM);
    conv2_pool_kernel<<<B, 224, CONV2_SMEM>>>(x, W2, b2, B);

    fc1_kernel<<<B / 32, 256>>>(Wl1, bl1);

    fc2_kernel<<<(B + 7) / 8, 256>>>(Wl2, bl2, out, B);
}

// round 3
// speedup vs baseline: 1.2836x; 1.2836x over previous
#include <cuda_runtime.h>
#include <cuda_bf16.h>
#include <cstdint>

// ---------------------------------------------------------------------------
// Net_23905787969856 on GB300 (compute_103 PTX -> no tcgen05; use mma.sync):
//  conv1: fp32 SIMT -> bf16 hi/lo padded planes (NHWC, 30x30)
//  conv2: warp-level bf16 mma.sync split-precision implicit GEMM
//         + fused bias/mask/relu/2x2-pool, output NHWC-pooled
//  fc1:   fp32 SIMT GEMM (Wl1 rows permuted for NHWC-pooled features)
//  fc2:   fp32 + log_softmax
// ---------------------------------------------------------------------------

#define BATCH 4096
#define HW 784
#define PHW 900            // 30*30 padded
#define C1 32
#define C2 64
#define POOLHW 196
#define FEAT 12544
#define HID 128

__device__ unsigned short g_h1hi[(size_t)BATCH * PHW * C1];
__device__ unsigned short g_h1lo[(size_t)BATCH * PHW * C1];
__device__ float g_h2[(size_t)BATCH * FEAT];   // [B][pos(196)][co(64)] NHWC-pooled
__device__ float g_h3[(size_t)BATCH * HID];

__device__ __forceinline__ uint32_t smem_u32(const void* p) {
    uint32_t a;
    asm("{ .reg .u64 t; cvta.to.shared.u64 t, %1; cvt.u32.u64 %0, t; }"
        : "=r"(a) : "l"(p));
    return a;
}

__device__ __forceinline__ void ldm_x4(uint32_t addr, uint32_t& r0, uint32_t& r1,
                                       uint32_t& r2, uint32_t& r3) {
    asm volatile("ldmatrix.sync.aligned.m8n8.x4.shared.b16 {%0,%1,%2,%3}, [%4];"
                 : "=r"(r0), "=r"(r1), "=r"(r2), "=r"(r3) : "r"(addr));
}

__device__ __forceinline__ void mma_bf16(float* c, uint32_t a0, uint32_t a1,
                                         uint32_t a2, uint32_t a3,
                                         uint32_t b0, uint32_t b1) {
    asm volatile(
        "mma.sync.aligned.m16n8k16.row.col.f32.bf16.bf16.f32 "
        "{%0,%1,%2,%3}, {%4,%5,%6,%7}, {%8,%9}, {%0,%1,%2,%3};"
        : "+f"(c[0]), "+f"(c[1]), "+f"(c[2]), "+f"(c[3])
        : "r"(a0), "r"(a1), "r"(a2), "r"(a3), "r"(b0), "r"(b1));
}

__device__ __forceinline__ void split_bf16(float v, unsigned short& h, unsigned short& l) {
    __nv_bfloat16 bh = __float2bfloat16(v);
    float fh = __bfloat162float(bh);
    __nv_bfloat16 bl = __float2bfloat16(v - fh);
    h = __bfloat16_as_ushort(bh);
    l = __bfloat16_as_ushort(bl);
}

// ===========================================================================
// Kernel 1: conv1 + bias + mask + relu -> bf16 hi/lo planes, padded 30x30.
// ===========================================================================
__global__ void conv1_kernel(const float* __restrict__ x,
                             const float* __restrict__ W1,
                             const float* __restrict__ b1, int B) {
    __shared__ float w1s[C1 * 9];
    __shared__ float b1s[C1];
    int tid = threadIdx.x;
    for (int i = tid; i < C1 * 9; i += blockDim.x) w1s[i] = W1[i];
    if (tid < C1) b1s[tid] = b1[tid];
    __syncthreads();

    long long id = (long long)blockIdx.x * blockDim.x + tid;
    long long total = (long long)B * PHW * C1;
    if (id >= total) return;
    int c = (int)(id & 31);
    long long rest = id >> 5;
    int ppos = (int)(rest % PHW);
    int b = (int)(rest / PHW);
    int py = ppos / 30, px = ppos % 30;

    float o = 0.0f;
    if (py >= 1 && py <= 28 && px >= 1 && px <= 28) {
        int y = py - 1, xx = px - 1;
        const float* xb = x + (size_t)b * HW;
        float cen = xb[y * 28 + xx];
        float acc = b1s[c];
#pragma unroll
        for (int ky = 0; ky < 3; ky++) {
            int iy = y + ky - 1;
            if (iy < 0 || iy >= 28) continue;
#pragma unroll
            for (int kx = 0; kx < 3; kx++) {
                int ix = xx + kx - 1;
                if (ix < 0 || ix >= 28) continue;
                acc += w1s[c * 9 + ky * 3 + kx] * xb[iy * 28 + ix];
            }
        }
        o = (cen != 0.0f) ? fmaxf(acc, 0.0f) : 0.0f;
    }
    unsigned short hh, ll;
    split_bf16(o, hh, ll);
    g_h1hi[id] = hh;
    g_h1lo[id] = ll;
}

// ===========================================================================
// Kernel 2: conv2 via mma.sync bf16 split precision.
// CTA = (image, mtile of 4 rows = 112 pixels). 7 warps x m16. N=64, K=288.
// ===========================================================================
#define MT_PIX 112
#define KSTEPS 18
#define KSTRIDE 296                      // elements, row stride (pad 288 -> 296)
#define ROWB (KSTRIDE * 2)               // 592 bytes per row
#define A_PLANE (MT_PIX * ROWB)          // 66304
#define B_PLANE (64 * ROWB)              // 37888
#define OFF_AHI 0
#define OFF_ALO (OFF_AHI + A_PLANE)      // 66304
#define OFF_BHI (OFF_ALO + A_PLANE)      // 132608
#define OFF_BLO (OFF_BHI + B_PLANE)      // 170496
#define CONV2_SMEM (OFF_BLO + B_PLANE)   // 208384
#define SMO_STRIDE 72                    // floats, epilogue buffer stride

__global__ __launch_bounds__(224, 1)
void conv2_mma_kernel(const float* __restrict__ x,
                      const float* __restrict__ W2,
                      const float* __restrict__ b2) {
    extern __shared__ char sm[];
    uint32_t smb = smem_u32(sm);
    int tid = threadIdx.x;
    int wid = tid >> 5, lane = tid & 31;
    int b = blockIdx.x / 7;
    int mt = blockIdx.x % 7;

    // ---- build A hi/lo: im2col from padded h1 planes. A[p][t*32+ci]
    {
        const unsigned short* h1h = g_h1hi + (size_t)b * PHW * C1;
        const unsigned short* h1l = g_h1lo + (size_t)b * PHW * C1;
        for (int task = tid; task < MT_PIX * 9; task += 224) {
            int p = task / 9, t = task % 9;
            int y = mt * 4 + p / 28;
            int xx = p % 28;
            int src = (y + t / 3) * 30 + (xx + t % 3);
            const uint4* sh = (const uint4*)(h1h + (size_t)src * C1);
            const uint4* sl = (const uint4*)(h1l + (size_t)src * C1);
            char* dh = sm + OFF_AHI + p * ROWB + t * 64;
            char* dl = sm + OFF_ALO + p * ROWB + t * 64;
#pragma unroll
            for (int g = 0; g < 4; g++) {
                ((uint4*)dh)[g] = sh[g];
                ((uint4*)dl)[g] = sl[g];
            }
        }
    }
    // ---- build B hi/lo: B[co][t*32+ci] = split(W2[co*288 + ci*9 + t])
    for (int i = tid; i < 64 * 9 * 4; i += 224) {
        int co = i / 36;
        int r = i % 36;
        int t = r / 4;
        int ci0 = (r % 4) * 8;
        unsigned short vh[8], vl[8];
#pragma unroll
        for (int j = 0; j < 8; j++) {
            float w = __ldg(&W2[co * 288 + (ci0 + j) * 9 + t]);
            split_bf16(w, vh[j], vl[j]);
        }
        int off = co * ROWB + (t * 32 + ci0) * 2;
        *(uint4*)(sm + OFF_BHI + off) = *(const uint4*)vh;
        *(uint4*)(sm + OFF_BLO + off) = *(const uint4*)vl;
    }
    __syncthreads();

    // ---- MMA mainloop
    float acc[8][4];
#pragma unroll
    for (int n = 0; n < 8; n++)
#pragma unroll
        for (int j = 0; j < 4; j++) acc[n][j] = 0.0f;

    uint32_t lrow = (uint32_t)(lane & 15);
    uint32_t koff = (uint32_t)((lane >> 4) * 16);   // bytes: (lane>>4)*8 elems *2
    uint32_t aHi = smb + OFF_AHI + (wid * 16 + lrow) * ROWB + koff;
    uint32_t aLo = smb + OFF_ALO + (wid * 16 + lrow) * ROWB + koff;
    uint32_t bHi = smb + OFF_BHI + lrow * ROWB + koff;
    uint32_t bLo = smb + OFF_BLO + lrow * ROWB + koff;

#pragma unroll 1
    for (int k = 0; k < KSTEPS; k++) {
        uint32_t kb = (uint32_t)k * 32;   // 16 bf16 = 32 bytes
        uint32_t ah0, ah1, ah2, ah3, al0, al1, al2, al3;
        ldm_x4(aHi + kb, ah0, ah1, ah2, ah3);
        ldm_x4(aLo + kb, al0, al1, al2, al3);
        uint32_t bh[16];
#pragma unroll
        for (int g2 = 0; g2 < 4; g2++)
            ldm_x4(bHi + g2 * 16 * ROWB + kb, bh[g2 * 4], bh[g2 * 4 + 1],
                   bh[g2 * 4 + 2], bh[g2 * 4 + 3]);
#pragma unroll
        for (int g2 = 0; g2 < 4; g2++) {
            mma_bf16(acc[g2 * 2],     ah0, ah1, ah2, ah3, bh[g2 * 4],     bh[g2 * 4 + 2]);
            mma_bf16(acc[g2 * 2 + 1], ah0, ah1, ah2, ah3, bh[g2 * 4 + 1], bh[g2 * 4 + 3]);
            mma_bf16(acc[g2 * 2],     al0, al1, al2, al3, bh[g2 * 4],     bh[g2 * 4 + 2]);
            mma_bf16(acc[g2 * 2 + 1], al0, al1, al2, al3, bh[g2 * 4 + 1], bh[g2 * 4 + 3]);
        }
        uint32_t bl[16];
#pragma unroll
        for (int g2 = 0; g2 < 4; g2++)
            ldm_x4(bLo + g2 * 16 * ROWB + kb, bl[g2 * 4], bl[g2 * 4 + 1],
                   bl[g2 * 4 + 2], bl[g2 * 4 + 3]);
#pragma unroll
        for (int g2 = 0; g2 < 4; g2++) {
            mma_bf16(acc[g2 * 2],     ah0, ah1, ah2, ah3, bl[g2 * 4],     bl[g2 * 4 + 2]);
            mma_bf16(acc[g2 * 2 + 1], ah0, ah1, ah2, ah3, bl[g2 * 4 + 1], bl[g2 * 4 + 3]);
        }
    }
    __syncthreads();   // done reading A/B smem; reuse as epilogue buffer

    // ---- epilogue: bias + mask + relu into smem [112][SMO_STRIDE]
    float* smo = (float*)sm;
    {
        int p0 = wid * 16 + lane / 4;       // pixel for c0,c1
        int p1 = p0 + 8;                    // pixel for c2,c3
        bool m0 = __ldg(&x[(size_t)b * HW + mt * MT_PIX + p0]) != 0.0f;
        bool m1 = __ldg(&x[(size_t)b * HW + mt * MT_PIX + p1]) != 0.0f;
#pragma unroll
        for (int nt = 0; nt < 8; nt++) {
            int c0 = nt * 8 + (lane % 4) * 2;
            float bb0 = __ldg(&b2[c0]);
            float bb1 = __ldg(&b2[c0 + 1]);
            smo[p0 * SMO_STRIDE + c0]     = m0 ? fmaxf(acc[nt][0] + bb0, 0.0f) : 0.0f;
            smo[p0 * SMO_STRIDE + c0 + 1] = m0 ? fmaxf(acc[nt][1] + bb1, 0.0f) : 0.0f;
            smo[p1 * SMO_STRIDE + c0]     = m1 ? fmaxf(acc[nt][2] + bb0, 0.0f) : 0.0f;
            smo[p1 * SMO_STRIDE + c0 + 1] = m1 ? fmaxf(acc[nt][3] + bb1, 0.0f) : 0.0f;
        }
    }
    __syncthreads();

    // ---- 2x2 maxpool -> g_h2 NHWC-pooled [b][pos][co], float4 coalesced
    for (int i = tid; i < 28 * 16; i += 224) {
        int pos = i / 16, c4 = i % 16;
        int pri = pos / 14, pc = pos % 14;
        int p00 = pri * 56 + pc * 2;       // local pixel of top-left
        const float4 v00 = *(const float4*)&smo[p00 * SMO_STRIDE + c4 * 4];
        const float4 v01 = *(const float4*)&smo[(p00 + 1) * SMO_STRIDE + c4 * 4];
        const float4 v10 = *(const float4*)&smo[(p00 + 28) * SMO_STRIDE + c4 * 4];
        const float4 v11 = *(const float4*)&smo[(p00 + 29) * SMO_STRIDE + c4 * 4];
        float4 r;
        r.x = fmaxf(fmaxf(v00.x, v01.x), fmaxf(v10.x, v11.x));
        r.y = fmaxf(fmaxf(v00.y, v01.y), fmaxf(v10.y, v11.y));
        r.z = fmaxf(fmaxf(v00.z, v01.z), fmaxf(v10.z, v11.z));
        r.w = fmaxf(fmaxf(v00.w, v01.w), fmaxf(v10.w, v11.w));
        int gpos = (mt * 2 + pri) * 14 + pc;
        *(float4*)&g_h2[(size_t)b * FEAT + gpos * 64 + c4 * 4] = r;
    }
}

// ===========================================================================
// Kernel 3: FC1 fp32 GEMM, A = g_h2 (NHWC-pooled features), B rows permuted.
// feature k = pos*64+co  ->  Wl1 row = co*196 + pos
// ===========================================================================
__global__ __launch_bounds__(256)
void fc1_kernel(const float* __restrict__ Wl1, const float* __restrict__ bl1) {
    __shared__ float As[32][36];
    __shared__ float Bs[32][128];

    int tid = threadIdx.x;
    int rowBase = blockIdx.x * 32;
    int tx = tid % 32, ty = tid / 32;
    int ar = tid / 8, ac4 = tid % 8;

    float acc[4][4] = {};

    for (int k0 = 0; k0 < FEAT; k0 += 32) {
        float4 av = *(const float4*)&g_h2[(size_t)(rowBase + ar) * FEAT + k0 + ac4 * 4];
        *(float4*)&As[ar][ac4 * 4] = av;
#pragma unroll
        for (int i = 0; i < 4; i++) {
            int f = i * 256 + tid;
            int r = f / 32, c4 = f % 32;
            int k = k0 + r;
            int wrow = (k & 63) * POOLHW + (k >> 6);   // permuted row
            *(float4*)&Bs[r][c4 * 4] = *(const float4*)&Wl1[(size_t)wrow * HID + c4 * 4];
        }
        __syncthreads();
#pragma unroll
        for (int kk = 0; kk < 32; kk++) {
            float a0 = As[ty * 4 + 0][kk];
            float a1 = As[ty * 4 + 1][kk];
            float a2 = As[ty * 4 + 2][kk];
            float a3 = As[ty * 4 + 3][kk];
            float4 bv = *(const float4*)&Bs[kk][tx * 4];
            acc[0][0] += a0 * bv.x; acc[0][1] += a0 * bv.y; acc[0][2] += a0 * bv.z; acc[0][3] += a0 * bv.w;
            acc[1][0] += a1 * bv.x; acc[1][1] += a1 * bv.y; acc[1][2] += a1 * bv.z; acc[1][3] += a1 * bv.w;
            acc[2][0] += a2 * bv.x; acc[2][1] += a2 * bv.y; acc[2][2] += a2 * bv.z; acc[2][3] += a2 * bv.w;
            acc[3][0] += a3 * bv.x; acc[3][1] += a3 * bv.y; acc[3][2] += a3 * bv.z; acc[3][3] += a3 * bv.w;
        }
        __syncthreads();
    }

    float4 bl = *(const float4*)&bl1[tx * 4];
#pragma unroll
    for (int i = 0; i < 4; i++) {
        int row = rowBase + ty * 4 + i;
        float4 v;
        v.x = fmaxf(acc[i][0] + bl.x, 0.0f);
        v.y = fmaxf(acc[i][1] + bl.y, 0.0f);
        v.z = fmaxf(acc[i][2] + bl.z, 0.0f);
        v.w = fmaxf(acc[i][3] + bl.w, 0.0f);
        *(float4*)&g_h3[(size_t)row * HID + tx * 4] = v;
    }
}

// ===========================================================================
// Kernel 4: FC2 (128->10) + log_softmax.
// ===========================================================================
__global__ __launch_bounds__(256)
void fc2_kernel(const float* __restrict__ Wl2, const float* __restrict__ bl2,
                float* __restrict__ out, int B) {
    __shared__ float ws[128 * 10];
    __shared__ float bs[10];
    int tid = threadIdx.x;
    for (int i = tid; i < 1280; i += 256) ws[i] = Wl2[i];
    if (tid < 10) bs[tid] = bl2[tid];
    __syncthreads();

    int w = blockIdx.x * 8 + tid / 32;
    int lane = tid % 32;
    if (w >= B) return;

    const float* h = g_h3 + (size_t)w * HID;
    float acc[10];
#pragma unroll
    for (int j = 0; j < 10; j++) acc[j] = 0.0f;
#pragma unroll
    for (int i = 0; i < 4; i++) {
        int kk = lane + 32 * i;
        float hv = h[kk];
        const float* wr = &ws[kk * 10];
#pragma unroll
        for (int j = 0; j < 10; j++) acc[j] += hv * wr[j];
    }
#pragma unroll
    for (int j = 0; j < 10; j++) {
#pragma unroll
        for (int off = 16; off > 0; off >>= 1)
            acc[j] += __shfl_xor_sync(0xffffffffu, acc[j], off);
    }
    if (lane == 0) {
        float z[10];
        float mx = -1e30f;
#pragma unroll
        for (int j = 0; j < 10; j++) { z[j] = acc[j] + bs[j]; mx = fmaxf(mx, z[j]); }
        float s = 0.0f;
#pragma unroll
        for (int j = 0; j < 10; j++) s += expf(z[j] - mx);
        float l = logf(s);
#pragma unroll
        for (int j = 0; j < 10; j++) out[(size_t)w * 10 + j] = z[j] - mx - l;
    }
}

// ===========================================================================
extern "C" void kernel_launch(void* const* d_in, const int* in_sizes, int n_in,
                              void* d_out, int out_size) {
    const float* x   = (const float*)d_in[0];
    const float* W1  = (const float*)d_in[1];
    const float* b1  = (const float*)d_in[2];
    const float* W2  = (const float*)d_in[3];
    const float* b2  = (const float*)d_in[4];
    const float* Wl1 = (const float*)d_in[5];
    const float* bl1 = (const float*)d_in[6];
    const float* Wl2 = (const float*)d_in[7];
    const float* bl2 = (const float*)d_in[8];
    float* out = (float*)d_out;

    int B = in_sizes[0] / HW;   // 4096

    long long total1 = (long long)B * PHW * C1;
    conv1_kernel<<<(int)((total1 + 255) / 256), 256>>>(x, W1, b1, B);

    cudaFuncSetAttribute(conv2_mma_kernel,
                         cudaFuncAttributeMaxDynamicSharedMemorySize, CONV2_SMEM);
    conv2_mma_kernel<<<B * 7, 224, CONV2_SMEM>>>(x, W2, b2);

    fc1_kernel<<<B / 32, 256>>>(Wl1, bl1);

    fc2_kernel<<<(B + 7) / 8, 256>>>(Wl2, bl2, out, B);
}

// round 4
// speedup vs baseline: 2.4604x; 1.9168x over previous
#include <cuda_runtime.h>
#include <cuda_fp16.h>
#include <cstdint>

// ---------------------------------------------------------------------------
// Net_23905787969856 on GB300 (compute_103 PTX => mma.sync fp16 path):
//  prep:  W2 -> im2col-ordered fp16 [64][296]; Wl1 -> permuted transposed
//         fp16 hi/lo [128][12544]
//  conv1: fp32 SIMT -> fp16 hi/lo padded planes (NHWC 30x30x32)
//  conv2: mma.sync fp16, A gathered from raw image via ldmatrix lane pointers
//         (no im2col), A split hi/lo (2 passes), B single fp16;
//         fused bias/mask/relu/2x2-pool -> h2 fp16 hi/lo NHWC-pooled
//  fc1:   mma.sync fp16 3-pass split GEMM + bias + relu -> fp32
//  fc2:   fp32 + log_softmax
// ---------------------------------------------------------------------------

#define BATCH 4096
#define HW 784
#define PHW 900
#define C1 32
#define POOLHW 196
#define FEAT 12544
#define HID 128

__device__ __half g_h1hi[(size_t)BATCH * PHW * C1];
__device__ __half g_h1lo[(size_t)BATCH * PHW * C1];
__device__ __half g_h2hi[(size_t)BATCH * FEAT];   // [B][pos][co] NHWC-pooled
__device__ __half g_h2lo[(size_t)BATCH * FEAT];
__device__ __half g_w2[64 * 296];                 // [co][t*32+ci] fp16
__device__ __half g_wl1hi[(size_t)HID * FEAT];    // [n][k] permuted
__device__ __half g_wl1lo[(size_t)HID * FEAT];
__device__ float g_h3[(size_t)BATCH * HID];

__device__ __forceinline__ uint32_t smem_u32(const void* p) {
    uint32_t a;
    asm("{ .reg .u64 t; cvta.to.shared.u64 t, %1; cvt.u32.u64 %0, t; }"
        : "=r"(a) : "l"(p));
    return a;
}
__device__ __forceinline__ void ldm_x4(uint32_t addr, uint32_t& r0, uint32_t& r1,
                                       uint32_t& r2, uint32_t& r3) {
    asm volatile("ldmatrix.sync.aligned.m8n8.x4.shared.b16 {%0,%1,%2,%3}, [%4];"
                 : "=r"(r0), "=r"(r1), "=r"(r2), "=r"(r3) : "r"(addr));
}
__device__ __forceinline__ void mma_f16(float* c, uint32_t a0, uint32_t a1,
                                        uint32_t a2, uint32_t a3,
                                        uint32_t b0, uint32_t b1) {
    asm volatile(
        "mma.sync.aligned.m16n8k16.row.col.f32.f16.f16.f32 "
        "{%0,%1,%2,%3}, {%4,%5,%6,%7}, {%8,%9}, {%0,%1,%2,%3};"
        : "+f"(c[0]), "+f"(c[1]), "+f"(c[2]), "+f"(c[3])
        : "r"(a0), "r"(a1), "r"(a2), "r"(a3), "r"(b0), "r"(b1));
}
__device__ __forceinline__ void split_f16(float v, __half& h, __half& l) {
    h = __float2half_rn(v);
    l = __float2half_rn(v - __half2float(h));
}

// ===========================================================================
// Prep kernels (run every launch; cheap)
// ===========================================================================
__global__ void prep_w2_kernel(const float* __restrict__ W2) {
    int i = blockIdx.x * 256 + threadIdx.x;
    if (i >= 64 * 296) return;
    int co = i / 296, col = i % 296;
    float w = 0.0f;
    if (col < 288) {
        int t = col / 32, ci = col % 32;
        w = W2[co * 288 + ci * 9 + t];
    }
    g_w2[i] = __float2half_rn(w);
}

__global__ void prep_wl1_kernel(const float* __restrict__ Wl1) {
    int i = blockIdx.x * 256 + threadIdx.x;   // over 12544 * 16 n-chunks
    if (i >= FEAT * 16) return;
    int k = i / 16, nc = i % 16;
    int wrow = (k & 63) * POOLHW + (k >> 6);  // permuted Wl1 row
    const float4* src = (const float4*)&Wl1[(size_t)wrow * HID + nc * 8];
    float4 v0 = src[0], v1 = src[1];
    float vals[8] = {v0.x, v0.y, v0.z, v0.w, v1.x, v1.y, v1.z, v1.w};
#pragma unroll
    for (int j = 0; j < 8; j++) {
        __half h, l;
        split_f16(vals[j], h, l);
        size_t o = (size_t)(nc * 8 + j) * FEAT + k;
        g_wl1hi[o] = h;
        g_wl1lo[o] = l;
    }
}

// ===========================================================================
// Kernel 1: conv1 + bias + mask + relu -> fp16 hi/lo padded planes.
// ===========================================================================
__global__ void conv1_kernel(const float* __restrict__ x,
                             const float* __restrict__ W1,
                             const float* __restrict__ b1, int B) {
    __shared__ float w1s[C1 * 9];
    __shared__ float b1s[C1];
    int tid = threadIdx.x;
    for (int i = tid; i < C1 * 9; i += blockDim.x) w1s[i] = W1[i];
    if (tid < C1) b1s[tid] = b1[tid];
    __syncthreads();

    long long id = (long long)blockIdx.x * blockDim.x + tid;
    long long total = (long long)B * PHW * C1;
    if (id >= total) return;
    int c = (int)(id & 31);
    long long rest = id >> 5;
    int ppos = (int)(rest % PHW);
    int b = (int)(rest / PHW);
    int py = ppos / 30, px = ppos % 30;

    float o = 0.0f;
    if (py >= 1 && py <= 28 && px >= 1 && px <= 28) {
        int y = py - 1, xx = px - 1;
        const float* xb = x + (size_t)b * HW;
        float cen = xb[y * 28 + xx];
        float acc = b1s[c];
#pragma unroll
        for (int ky = 0; ky < 3; ky++) {
            int iy = y + ky - 1;
            if (iy < 0 || iy >= 28) continue;
#pragma unroll
            for (int kx = 0; kx < 3; kx++) {
                int ix = xx + kx - 1;
                if (ix < 0 || ix >= 28) continue;
                acc += w1s[c * 9 + ky * 3 + kx] * xb[iy * 28 + ix];
            }
        }
        o = (cen != 0.0f) ? fmaxf(acc, 0.0f) : 0.0f;
    }
    __half h, l;
    split_f16(o, h, l);
    g_h1hi[id] = h;
    g_h1lo[id] = l;
}

// ===========================================================================
// Kernel 2: conv2 via mma.sync, A gathered from raw image (no im2col).
// CTA = (image, mtile of 4 rows = 112 px). 7 warps x m16, N=64, K=18x16.
// ===========================================================================
#define MT_PIX 112
#define PIXSTRIDE 40                       // fp16 elems per pixel (80 B, 16*odd)
#define APLANE (6 * 30 * PIXSTRIDE * 2)    // 14400 B per plane
#define B_OFF (2 * APLANE)                 // 28800
#define BROW 592                           // bytes per B row (296 fp16, 16*odd)
#define C2_SMEM (B_OFF + 64 * BROW)        // 66688
#define SMO_STRIDE 72

__global__ __launch_bounds__(224, 1)
void conv2_mma_kernel(const float* __restrict__ x, const float* __restrict__ b2) {
    extern __shared__ char sm[];
    uint32_t smb = smem_u32(sm);
    int tid = threadIdx.x;
    int wid = tid >> 5, lane = tid & 31;
    int b = blockIdx.x / 7;
    int mt = blockIdx.x % 7;

    // ---- load raw image rows [mt*4 .. mt*4+5], hi & lo planes, pixel stride 40
    {
        const uint4* sh = (const uint4*)(g_h1hi + (size_t)b * PHW * C1);
        const uint4* sl = (const uint4*)(g_h1lo + (size_t)b * PHW * C1);
        for (int i = tid; i < 720; i += 224) {          // 6*30*4 quads
            int r = i / 120, rem = i % 120;
            int px = rem / 4, q = rem % 4;
            int srcq = ((mt * 4 + r) * 30 + px) * 4 + q;    // quad index (8 ch)
            int dst = ((r * 30 + px) * PIXSTRIDE + q * 8) * 2;
            *(uint4*)(sm + dst) = sh[srcq];
            *(uint4*)(sm + APLANE + dst) = sl[srcq];
        }
    }
    // ---- load B (precomputed im2col weights), straight memcpy 37888 B
    {
        const uint4* src = (const uint4*)g_w2;
        for (int i = tid; i < 2368; i += 224)
            *(uint4*)(sm + B_OFF + i * 16) = src[i];
    }
    __syncthreads();

    float acc[8][4];
#pragma unroll
    for (int n = 0; n < 8; n++)
#pragma unroll
        for (int j = 0; j < 4; j++) acc[n][j] = 0.0f;

    int lr = lane & 15;
    int p = wid * 16 + lr;                  // pixel 0..111
    int py = p / 28, px = p % 28;
    uint32_t aBaseHi = smb + ((py * 30 + px) * PIXSTRIDE + (lane >> 4) * 8) * 2;
    uint32_t aBaseLo = aBaseHi + APLANE;
    uint32_t bBase = smb + B_OFF + lr * BROW + (lane >> 4) * 16;

#pragma unroll
    for (int s = 0; s < 18; s++) {
        const int t = s >> 1, h = s & 1;
        const int dy = t / 3, dx = t % 3;
        const uint32_t aoff = (uint32_t)(((dy * 30 + dx) * PIXSTRIDE + h * 16) * 2);
        const uint32_t kb = (uint32_t)s * 32;
        uint32_t ah0, ah1, ah2, ah3, al0, al1, al2, al3;
        ldm_x4(aBaseHi + aoff, ah0, ah1, ah2, ah3);
        ldm_x4(aBaseLo + aoff, al0, al1, al2, al3);
#pragma unroll
        for (int g2 = 0; g2 < 4; g2++) {
            uint32_t b0, b1, b2r, b3;
            ldm_x4(bBase + (uint32_t)(g2 * 16) * BROW + kb, b0, b1, b2r, b3);
            mma_f16(acc[g2 * 2],     ah0, ah1, ah2, ah3, b0, b2r);
            mma_f16(acc[g2 * 2 + 1], ah0, ah1, ah2, ah3, b1, b3);
            mma_f16(acc[g2 * 2],     al0, al1, al2, al3, b0, b2r);
            mma_f16(acc[g2 * 2 + 1], al0, al1, al2, al3, b1, b3);
        }
    }
    __syncthreads();   // reuse smem for epilogue

    // ---- epilogue: bias + mask + relu to smem [112][72] fp32
    float* smo = (float*)sm;
    {
        int p0 = wid * 16 + lane / 4;
        int p1 = p0 + 8;
        bool m0 = __ldg(&x[(size_t)b * HW + mt * MT_PIX + p0]) != 0.0f;
        bool m1 = __ldg(&x[(size_t)b * HW + mt * MT_PIX + p1]) != 0.0f;
#pragma unroll
        for (int nt = 0; nt < 8; nt++) {
            int c0 = nt * 8 + (lane % 4) * 2;
            float bb0 = __ldg(&b2[c0]);
            float bb1 = __ldg(&b2[c0 + 1]);
            smo[p0 * SMO_STRIDE + c0]     = m0 ? fmaxf(acc[nt][0] + bb0, 0.0f) : 0.0f;
            smo[p0 * SMO_STRIDE + c0 + 1] = m0 ? fmaxf(acc[nt][1] + bb1, 0.0f) : 0.0f;
            smo[p1 * SMO_STRIDE + c0]     = m1 ? fmaxf(acc[nt][2] + bb0, 0.0f) : 0.0f;
            smo[p1 * SMO_STRIDE + c0 + 1] = m1 ? fmaxf(acc[nt][3] + bb1, 0.0f) : 0.0f;
        }
    }
    __syncthreads();

    // ---- 2x2 maxpool -> h2 fp16 hi/lo NHWC-pooled, 8B stores
    for (int i = tid; i < 28 * 16; i += 224) {
        int pos = i / 16, c4 = i % 16;
        int pri = pos / 14, pc = pos % 14;
        int p00 = pri * 56 + pc * 2;
        const float4 v00 = *(const float4*)&smo[p00 * SMO_STRIDE + c4 * 4];
        const float4 v01 = *(const float4*)&smo[(p00 + 1) * SMO_STRIDE + c4 * 4];
        const float4 v10 = *(const float4*)&smo[(p00 + 28) * SMO_STRIDE + c4 * 4];
        const float4 v11 = *(const float4*)&smo[(p00 + 29) * SMO_STRIDE + c4 * 4];
        float r[4];
        r[0] = fmaxf(fmaxf(v00.x, v01.x), fmaxf(v10.x, v11.x));
        r[1] = fmaxf(fmaxf(v00.y, v01.y), fmaxf(v10.y, v11.y));
        r[2] = fmaxf(fmaxf(v00.z, v01.z), fmaxf(v10.z, v11.z));
        r[3] = fmaxf(fmaxf(v00.w, v01.w), fmaxf(v10.w, v11.w));
        __half hs[4], ls[4];
#pragma unroll
        for (int j = 0; j < 4; j++) split_f16(r[j], hs[j], ls[j]);
        int gpos = (mt * 2 + pri) * 14 + pc;
        size_t o = (size_t)b * FEAT + gpos * 64 + c4 * 4;
        *(uint2*)&g_h2hi[o] = *(const uint2*)hs;
        *(uint2*)&g_h2lo[o] = *(const uint2*)ls;
    }
}

// ===========================================================================
// Kernel 3: FC1 via mma.sync, 3-pass split. CTA M=32 N=128, 4 warps (2x2).
// ===========================================================================
#define AS_STRIDE 72                        // fp16 elems (144 B = 16*odd)
#define AS_BYTES (32 * AS_STRIDE * 2)       // 4608
#define BS_BYTES (128 * AS_STRIDE * 2)      // 18432
#define FC1_AHI 0
#define FC1_ALO (FC1_AHI + AS_BYTES)
#define FC1_BHI (FC1_ALO + AS_BYTES)
#define FC1_BLO (FC1_BHI + BS_BYTES)
#define FC1_SMEM (FC1_BLO + BS_BYTES)       // 46080

__global__ __launch_bounds__(128, 1)
void fc1_mma_kernel(const float* __restrict__ bl1) {
    extern __shared__ char sm[];
    uint32_t smb = smem_u32(sm);
    int tid = threadIdx.x;
    int wid = tid >> 5, lane = tid & 31;
    int rowBase = blockIdx.x * 32;

    float acc[8][4];
#pragma unroll
    for (int n = 0; n < 8; n++)
#pragma unroll
        for (int j = 0; j < 4; j++) acc[n][j] = 0.0f;

    int mrow = (wid >> 1) * 16;
    int nbase = (wid & 1) * 64;
    uint32_t aHi = smb + FC1_AHI + ((mrow + (lane & 15)) * AS_STRIDE + (lane >> 4) * 8) * 2;
    uint32_t aLo = aHi + AS_BYTES;
    uint32_t bHi = smb + FC1_BHI + ((nbase + (lane & 15)) * AS_STRIDE + (lane >> 4) * 8) * 2;
    uint32_t bLo = bHi + BS_BYTES;

    for (int k0 = 0; k0 < FEAT; k0 += 64) {
        // A tile: 32 rows x 64 k, hi+lo (256 quads each)
        for (int i = tid; i < 256; i += 128) {
            int r = i / 8, q = i % 8;
            size_t src = (size_t)(rowBase + r) * FEAT + k0 + q * 8;
            int dst = (r * AS_STRIDE + q * 8) * 2;
            *(uint4*)(sm + FC1_AHI + dst) = *(const uint4*)&g_h2hi[src];
            *(uint4*)(sm + FC1_ALO + dst) = *(const uint4*)&g_h2lo[src];
        }
        // B tile: 128 n-rows x 64 k, hi+lo (1024 quads each)
        for (int i = tid; i < 1024; i += 128) {
            int n = i / 8, q = i % 8;
            size_t src = (size_t)n * FEAT + k0 + q * 8;
            int dst = (n * AS_STRIDE + q * 8) * 2;
            *(uint4*)(sm + FC1_BHI + dst) = *(const uint4*)&g_wl1hi[src];
            *(uint4*)(sm + FC1_BLO + dst) = *(const uint4*)&g_wl1lo[src];
        }
        __syncthreads();

#pragma unroll
        for (int ks = 0; ks < 4; ks++) {
            uint32_t kb = (uint32_t)ks * 32;   // 16 elems * 2B
            uint32_t ah0, ah1, ah2, ah3, al0, al1, al2, al3;
            ldm_x4(aHi + kb, ah0, ah1, ah2, ah3);
            ldm_x4(aLo + kb, al0, al1, al2, al3);
#pragma unroll
            for (int g2 = 0; g2 < 4; g2++) {
                uint32_t h0, h1, h2r, h3;
                ldm_x4(bHi + (uint32_t)(g2 * 16 * AS_STRIDE * 2) + kb, h0, h1, h2r, h3);
                mma_f16(acc[g2 * 2],     ah0, ah1, ah2, ah3, h0, h2r);
                mma_f16(acc[g2 * 2 + 1], ah0, ah1, ah2, ah3, h1, h3);
                mma_f16(acc[g2 * 2],     al0, al1, al2, al3, h0, h2r);
                mma_f16(acc[g2 * 2 + 1], al0, al1, al2, al3, h1, h3);
                uint32_t l0, l1, l2r, l3;
                ldm_x4(bLo + (uint32_t)(g2 * 16 * AS_STRIDE * 2) + kb, l0, l1, l2r, l3);
                mma_f16(acc[g2 * 2],     ah0, ah1, ah2, ah3, l0, l2r);
                mma_f16(acc[g2 * 2 + 1], ah0, ah1, ah2, ah3, l1, l3);
            }
        }
        __syncthreads();
    }

    // epilogue: bias + relu -> g_h3 fp32
    int r0 = rowBase + mrow + lane / 4;
#pragma unroll
    for (int nt = 0; nt < 8; nt++) {
        int c0 = nbase + nt * 8 + (lane % 4) * 2;
        float bb0 = __ldg(&bl1[c0]);
        float bb1 = __ldg(&bl1[c0 + 1]);
        g_h3[(size_t)r0 * HID + c0]           = fmaxf(acc[nt][0] + bb0, 0.0f);
        g_h3[(size_t)r0 * HID + c0 + 1]       = fmaxf(acc[nt][1] + bb1, 0.0f);
        g_h3[(size_t)(r0 + 8) * HID + c0]     = fmaxf(acc[nt][2] + bb0, 0.0f);
        g_h3[(size_t)(r0 + 8) * HID + c0 + 1] = fmaxf(acc[nt][3] + bb1, 0.0f);
    }
}

// ===========================================================================
// Kernel 4: FC2 (128->10) + log_softmax.
// ===========================================================================
__global__ __launch_bounds__(256)
void fc2_kernel(const float* __restrict__ Wl2, const float* __restrict__ bl2,
                float* __restrict__ out, int B) {
    __shared__ float ws[128 * 10];
    __shared__ float bs[10];
    int tid = threadIdx.x;
    for (int i = tid; i < 1280; i += 256) ws[i] = Wl2[i];
    if (tid < 10) bs[tid] = bl2[tid];
    __syncthreads();

    int w = blockIdx.x * 8 + tid / 32;
    int lane = tid % 32;
    if (w >= B) return;

    const float* h = g_h3 + (size_t)w * HID;
    float acc[10];
#pragma unroll
    for (int j = 0; j < 10; j++) acc[j] = 0.0f;
#pragma unroll
    for (int i = 0; i < 4; i++) {
        int kk = lane + 32 * i;
        float hv = h[kk];
        const float* wr = &ws[kk * 10];
#pragma unroll
        for (int j = 0; j < 10; j++) acc[j] += hv * wr[j];
    }
#pragma unroll
    for (int j = 0; j < 10; j++) {
#pragma unroll
        for (int off = 16; off > 0; off >>= 1)
            acc[j] += __shfl_xor_sync(0xffffffffu, acc[j], off);
    }
    if (lane == 0) {
        float z[10];
        float mx = -1e30f;
#pragma unroll
        for (int j = 0; j < 10; j++) { z[j] = acc[j] + bs[j]; mx = fmaxf(mx, z[j]); }
        float s = 0.0f;
#pragma unroll
        for (int j = 0; j < 10; j++) s += expf(z[j] - mx);
        float l = logf(s);
#pragma unroll
        for (int j = 0; j < 10; j++) out[(size_t)w * 10 + j] = z[j] - mx - l;
    }
}

// ===========================================================================
extern "C" void kernel_launch(void* const* d_in, const int* in_sizes, int n_in,
                              void* d_out, int out_size) {
    const float* x   = (const float*)d_in[0];
    const float* W1  = (const float*)d_in[1];
    const float* b1  = (const float*)d_in[2];
    const float* W2  = (const float*)d_in[3];
    const float* b2  = (const float*)d_in[4];
    const float* Wl1 = (const float*)d_in[5];
    const float* bl1 = (const float*)d_in[6];
    const float* Wl2 = (const float*)d_in[7];
    const float* bl2 = (const float*)d_in[8];
    float* out = (float*)d_out;

    int B = in_sizes[0] / HW;   // 4096

    prep_w2_kernel<<<(64 * 296 + 255) / 256, 256>>>(W2);
    prep_wl1_kernel<<<(FEAT * 16 + 255) / 256, 256>>>(Wl1);

    long long total1 = (long long)B * PHW * C1;
    conv1_kernel<<<(int)((total1 + 255) / 256), 256>>>(x, W1, b1, B);

    cudaFuncSetAttribute(conv2_mma_kernel,
                         cudaFuncAttributeMaxDynamicSharedMemorySize, C2_SMEM);
    conv2_mma_kernel<<<B * 7, 224, C2_SMEM>>>(x, b2);

    cudaFuncSetAttribute(fc1_mma_kernel,
                         cudaFuncAttributeMaxDynamicSharedMemorySize, FC1_SMEM);
    fc1_mma_kernel<<<B / 32, 128, FC1_SMEM>>>(bl1);

    fc2_kernel<<<(B + 7) / 8, 256>>>(Wl2, bl2, out, B);
}

// round 6
// speedup vs baseline: 5.6239x; 2.2858x over previous
#include <cuda_runtime.h>
#include <cuda_fp16.h>
#include <cstdint>

// ---------------------------------------------------------------------------
// Net_23905787969856 on GB300 (compute_103 => mma.sync fp16):
//  prep:   W2 -> im2col fp16 [64][296]; Wl1 -> permuted transposed fp16 [128][12544]
//  conv12: fused conv1(fp32, in-smem) + conv2 (mma.sync fp16, single A pass)
//          + bias/mask/relu/2x2-pool -> h2 fp16 hi/lo NHWC-pooled
//  fc1:    mma.sync 2-pass (A hi/lo x B fp16), M128/N128 tiles, split-K=4,
//          cp.async double buffered -> fp32 partials -> reduce+bias+relu
//  fc2:    fp32 + log_softmax
// ---------------------------------------------------------------------------

#define BATCH 4096
#define HW 784
#define C1 32
#define POOLHW 196
#define FEAT 12544
#define HID 128

__device__ __half g_h2hi[(size_t)BATCH * FEAT];
__device__ __half g_h2lo[(size_t)BATCH * FEAT];
__device__ __half g_w2[64 * 296];                 // [co][t*32+ci]
__device__ __half g_wl1[(size_t)HID * FEAT];      // [n][k] permuted
__device__ float g_fc1part[(size_t)4 * BATCH * HID];
__device__ float g_h3[(size_t)BATCH * HID];

__device__ __forceinline__ uint32_t smem_u32(const void* p) {
    uint32_t a;
    asm("{ .reg .u64 t; cvta.to.shared.u64 t, %1; cvt.u32.u64 %0, t; }"
        : "=r"(a) : "l"(p));
    return a;
}
__device__ __forceinline__ void ldm_x4(uint32_t addr, uint32_t& r0, uint32_t& r1,
                                       uint32_t& r2, uint32_t& r3) {
    asm volatile("ldmatrix.sync.aligned.m8n8.x4.shared.b16 {%0,%1,%2,%3}, [%4];"
                 : "=r"(r0), "=r"(r1), "=r"(r2), "=r"(r3) : "r"(addr));
}
__device__ __forceinline__ void mma_f16(float* c, uint32_t a0, uint32_t a1,
                                        uint32_t a2, uint32_t a3,
                                        uint32_t b0, uint32_t b1) {
    asm volatile(
        "mma.sync.aligned.m16n8k16.row.col.f32.f16.f16.f32 "
        "{%0,%1,%2,%3}, {%4,%5,%6,%7}, {%8,%9}, {%0,%1,%2,%3};"
        : "+f"(c[0]), "+f"(c[1]), "+f"(c[2]), "+f"(c[3])
        : "r"(a0), "r"(a1), "r"(a2), "r"(a3), "r"(b0), "r"(b1));
}
__device__ __forceinline__ void split_f16(float v, __half& h, __half& l) {
    h = __float2half_rn(v);
    l = __float2half_rn(v - __half2float(h));
}
#define CP_ASYNC16(dst, src) \
    asm volatile("cp.async.cg.shared.global [%0], [%1], 16;" :: "r"(dst), "l"(src))
#define CP_COMMIT() asm volatile("cp.async.commit_group;" ::: "memory")
#define CP_WAIT0()  asm volatile("cp.async.wait_group 0;" ::: "memory")

// ===========================================================================
// Prep kernels
// ===========================================================================
__global__ void prep_w2_kernel(const float* __restrict__ W2) {
    int i = blockIdx.x * 256 + threadIdx.x;
    if (i >= 64 * 296) return;
    int co = i / 296, col = i % 296;
    float w = 0.0f;
    if (col < 288) {
        int t = col / 32, ci = col % 32;
        w = W2[co * 288 + ci * 9 + t];
    }
    g_w2[i] = __float2half_rn(w);
}

__global__ void prep_wl1_kernel(const float* __restrict__ Wl1) {
    int i = blockIdx.x * 256 + threadIdx.x;   // FEAT*16 tasks
    if (i >= FEAT * 16) return;
    int k = i / 16, nc = i % 16;
    int wrow = (k & 63) * POOLHW + (k >> 6);  // NHWC-pooled permutation
    const float4* src = (const float4*)&Wl1[(size_t)wrow * HID + nc * 8];
    float4 v0 = src[0], v1 = src[1];
    float vals[8] = {v0.x, v0.y, v0.z, v0.w, v1.x, v1.y, v1.z, v1.w};
#pragma unroll
    for (int j = 0; j < 8; j++)
        g_wl1[(size_t)(nc * 8 + j) * FEAT + k] = __float2half_rn(vals[j]);
}

// ===========================================================================
// conv12 fused kernel. CTA = (image, mtile of 4 rows = 112 px), 224 threads.
// ===========================================================================
#define MT_PIX 112
#define PIXSTRIDE 40
#define OFF_A 0                          // 6*30*40*2 = 14400
#define OFF_XS 14400                     // 8*32*4 = 1024
#define OFF_W1 15424                     // 288*4 = 1152
#define OFF_B1 16576                     // 128
#define OFF_B 16704                      // 64*592 = 37888
#define BROW 592
#define C12_SMEM (OFF_B + 64 * BROW)     // 54592
#define SMO_STRIDE 72

__global__ __launch_bounds__(224, 3)
void conv12_kernel(const float* __restrict__ x,
                   const float* __restrict__ W1, const float* __restrict__ b1,
                   const float* __restrict__ b2) {
    extern __shared__ char sm[];
    uint32_t smb = smem_u32(sm);
    float* xs = (float*)(sm + OFF_XS);       // [8][32]
    float* w1s = (float*)(sm + OFF_W1);
    float* b1s = (float*)(sm + OFF_B1);
    int tid = threadIdx.x;
    int wid = tid >> 5, lane = tid & 31;
    int b = blockIdx.x / 7;
    int mt = blockIdx.x % 7;

    // ---- load x slab (rows mt*4-2 .. mt*4+5, col j = imcol+1): FULL coverage
    for (int i = tid; i < 256; i += 224) {
        int r8 = i >> 5, j = i & 31;
        int imrow = mt * 4 - 2 + r8, imcol = j - 1;
        float v = 0.0f;
        if (imrow >= 0 && imrow < 28 && imcol >= 0 && imcol < 28)
            v = x[(size_t)b * HW + imrow * 28 + imcol];
        xs[r8 * 32 + j] = v;
    }
    // ---- conv1 weights / biases: FULL coverage (288 > 224!)
    for (int i = tid; i < 288; i += 224) w1s[i] = W1[i];
    if (tid < 32) b1s[tid] = b1[tid];
    {
        const uint4* src = (const uint4*)g_w2;
        for (int i = tid; i < 2368; i += 224)
            *(uint4*)(sm + OFF_B + i * 16) = src[i];
    }
    __syncthreads();

    // ---- conv1 -> A plane fp16 (padded 6x30x32, pixel stride 40)
    for (int i = tid; i < 5760; i += 224) {
        int c = i & 31;
        int pc = (i >> 5) % 30;
        int pr = i / 960;
        int imrow = mt * 4 + pr - 1;
        float val = 0.0f;
        if (imrow >= 0 && imrow < 28 && pc >= 1 && pc <= 28) {
            float cen = xs[(pr + 1) * 32 + pc];
            float acc = b1s[c];
#pragma unroll
            for (int ky = 0; ky < 3; ky++)
#pragma unroll
                for (int kx = 0; kx < 3; kx++)
                    acc += w1s[c * 9 + ky * 3 + kx] * xs[(pr + ky) * 32 + pc + kx - 1];
            val = (cen != 0.0f) ? fmaxf(acc, 0.0f) : 0.0f;
        }
        *(__half*)(sm + OFF_A + ((pr * 30 + pc) * PIXSTRIDE + c) * 2) = __float2half_rn(val);
    }
    __syncthreads();

    // ---- mma mainloop: M=112 (7 warps x m16), N=64, K=288
    float acc[8][4];
#pragma unroll
    for (int n = 0; n < 8; n++)
#pragma unroll
        for (int j = 0; j < 4; j++) acc[n][j] = 0.0f;

    int lr = lane & 15;
    int p = wid * 16 + lr;
    int py = p / 28, px = p % 28;
    uint32_t aBase = smb + OFF_A + ((py * 30 + px) * PIXSTRIDE + (lane >> 4) * 8) * 2;
    uint32_t bBase = smb + OFF_B + lr * BROW + (lane >> 4) * 16;

#pragma unroll
    for (int s = 0; s < 18; s++) {
        const int t = s >> 1, h = s & 1;
        const int dy = t / 3, dx = t % 3;
        const uint32_t aoff = (uint32_t)(((dy * 30 + dx) * PIXSTRIDE + h * 16) * 2);
        const uint32_t kb = (uint32_t)s * 32;
        uint32_t a0, a1, a2, a3;
        ldm_x4(aBase + aoff, a0, a1, a2, a3);
#pragma unroll
        for (int g2 = 0; g2 < 4; g2++) {
            uint32_t b0, b1r, b2r, b3;
            ldm_x4(bBase + (uint32_t)(g2 * 16) * BROW + kb, b0, b1r, b2r, b3);
            mma_f16(acc[g2 * 2],     a0, a1, a2, a3, b0, b2r);
            mma_f16(acc[g2 * 2 + 1], a0, a1, a2, a3, b1r, b3);
        }
    }
    __syncthreads();

    // ---- masks from xs (before smo overwrites it)
    int p0 = wid * 16 + lane / 4;
    int p1 = p0 + 8;
    bool m0 = xs[(p0 / 28 + 2) * 32 + (p0 % 28) + 1] != 0.0f;
    bool m1 = xs[(p1 / 28 + 2) * 32 + (p1 % 28) + 1] != 0.0f;
    __syncthreads();

    // ---- epilogue: bias+mask+relu into smo [112][72] fp32 (overlays A/xs/B)
    float* smo = (float*)sm;
#pragma unroll
    for (int nt = 0; nt < 8; nt++) {
        int c0 = nt * 8 + (lane % 4) * 2;
        float bb0 = __ldg(&b2[c0]);
        float bb1 = __ldg(&b2[c0 + 1]);
        smo[p0 * SMO_STRIDE + c0]     = m0 ? fmaxf(acc[nt][0] + bb0, 0.0f) : 0.0f;
        smo[p0 * SMO_STRIDE + c0 + 1] = m0 ? fmaxf(acc[nt][1] + bb1, 0.0f) : 0.0f;
        smo[p1 * SMO_STRIDE + c0]     = m1 ? fmaxf(acc[nt][2] + bb0, 0.0f) : 0.0f;
        smo[p1 * SMO_STRIDE + c0 + 1] = m1 ? fmaxf(acc[nt][3] + bb1, 0.0f) : 0.0f;
    }
    __syncthreads();

    // ---- 2x2 maxpool -> h2 fp16 hi/lo NHWC-pooled
    for (int i = tid; i < 28 * 16; i += 224) {
        int pos = i / 16, c4 = i % 16;
        int pri = pos / 14, pc = pos % 14;
        int p00 = pri * 56 + pc * 2;
        const float4 v00 = *(const float4*)&smo[p00 * SMO_STRIDE + c4 * 4];
        const float4 v01 = *(const float4*)&smo[(p00 + 1) * SMO_STRIDE + c4 * 4];
        const float4 v10 = *(const float4*)&smo[(p00 + 28) * SMO_STRIDE + c4 * 4];
        const float4 v11 = *(const float4*)&smo[(p00 + 29) * SMO_STRIDE + c4 * 4];
        float r[4];
        r[0] = fmaxf(fmaxf(v00.x, v01.x), fmaxf(v10.x, v11.x));
        r[1] = fmaxf(fmaxf(v00.y, v01.y), fmaxf(v10.y, v11.y));
        r[2] = fmaxf(fmaxf(v00.z, v01.z), fmaxf(v10.z, v11.z));
        r[3] = fmaxf(fmaxf(v00.w, v01.w), fmaxf(v10.w, v11.w));
        __half hs[4], ls[4];
#pragma unroll
        for (int j = 0; j < 4; j++) split_f16(r[j], hs[j], ls[j]);
        int gpos = (mt * 2 + pri) * 14 + pc;
        size_t o = (size_t)b * FEAT + gpos * 64 + c4 * 4;
        *(uint2*)&g_h2hi[o] = *(const uint2*)hs;
        *(uint2*)&g_h2lo[o] = *(const uint2*)ls;
    }
}

// ===========================================================================
// FC1: M=128,N=128 tile, split-K=4 (chunk 3136), 8 warps, cp.async 2-stage.
// 2 passes: (Ahi + Alo) x B(fp16). Partials to g_fc1part.
// ===========================================================================
#define FC1_RS 40                        // smem row stride in fp16
#define FC1_PLANE (128 * FC1_RS * 2)     // 10240 B
#define FC1_STAGE (3 * FC1_PLANE)        // Ahi, Alo, B
#define FC1_SMEM (2 * FC1_STAGE)         // 61440

__global__ __launch_bounds__(256, 2)
void fc1_mma_kernel() {
    extern __shared__ char sm[];
    uint32_t smb = smem_u32(sm);
    int tid = threadIdx.x;
    int wid = tid >> 5, lane = tid & 31;
    int mtile = blockIdx.x & 31;
    int ks = blockIdx.x >> 5;            // 0..3
    int rowBase = mtile * 128;
    int kbase = ks * 3136;

    float acc[2][8][4];
#pragma unroll
    for (int mf = 0; mf < 2; mf++)
#pragma unroll
        for (int n = 0; n < 8; n++)
#pragma unroll
            for (int j = 0; j < 4; j++) acc[mf][n][j] = 0.0f;

    int qrow = tid >> 2;         // 0..63 (+64 for second)
    int qq = tid & 3;

    auto load_stage = [&](int stg, int kpos) {
        uint32_t base = smb + stg * FC1_STAGE;
#pragma unroll
        for (int j = 0; j < 2; j++) {
            int row = qrow + j * 64;
            uint32_t dst = base + (uint32_t)(row * FC1_RS + qq * 8) * 2;
            const __half* sA = &g_h2hi[(size_t)(rowBase + row) * FEAT + kpos + qq * 8];
            CP_ASYNC16(dst, sA);
            const __half* sL = &g_h2lo[(size_t)(rowBase + row) * FEAT + kpos + qq * 8];
            CP_ASYNC16(dst + FC1_PLANE, sL);
            const __half* sB = &g_wl1[(size_t)row * FEAT + kpos + qq * 8];
            CP_ASYNC16(dst + 2 * FC1_PLANE, sB);
        }
    };

    int wm = wid >> 1, wn = wid & 1;
    uint32_t aOff = (uint32_t)((wm * 32 + (lane & 15)) * FC1_RS + (lane >> 4) * 8) * 2;
    uint32_t bOff = (uint32_t)((wn * 64 + (lane & 15)) * FC1_RS + (lane >> 4) * 8) * 2
                    + 2 * FC1_PLANE;

    load_stage(0, kbase);
    CP_COMMIT();

    int cur = 0;
    for (int it = 0; it < 98; it++) {
        CP_WAIT0();
        __syncthreads();
        if (it + 1 < 98) {
            load_stage(cur ^ 1, kbase + (it + 1) * 32);
            CP_COMMIT();
        }
        uint32_t stg = smb + cur * FC1_STAGE;
#pragma unroll
        for (int kk = 0; kk < 2; kk++) {
            uint32_t kb = (uint32_t)kk * 32;
            uint32_t bfr[16];
#pragma unroll
            for (int g2 = 0; g2 < 4; g2++)
                ldm_x4(stg + bOff + (uint32_t)(g2 * 16 * FC1_RS) * 2 + kb,
                       bfr[g2 * 4], bfr[g2 * 4 + 1], bfr[g2 * 4 + 2], bfr[g2 * 4 + 3]);
#pragma unroll
            for (int mf = 0; mf < 2; mf++) {
                uint32_t ah0, ah1, ah2, ah3, al0, al1, al2, al3;
                uint32_t am = stg + aOff + (uint32_t)(mf * 16 * FC1_RS) * 2 + kb;
                ldm_x4(am, ah0, ah1, ah2, ah3);
                ldm_x4(am + FC1_PLANE, al0, al1, al2, al3);
#pragma unroll
                for (int g2 = 0; g2 < 4; g2++) {
                    mma_f16(acc[mf][g2 * 2],     ah0, ah1, ah2, ah3, bfr[g2 * 4],     bfr[g2 * 4 + 2]);
                    mma_f16(acc[mf][g2 * 2 + 1], ah0, ah1, ah2, ah3, bfr[g2 * 4 + 1], bfr[g2 * 4 + 3]);
                    mma_f16(acc[mf][g2 * 2],     al0, al1, al2, al3, bfr[g2 * 4],     bfr[g2 * 4 + 2]);
                    mma_f16(acc[mf][g2 * 2 + 1], al0, al1, al2, al3, bfr[g2 * 4 + 1], bfr[g2 * 4 + 3]);
                }
            }
        }
        __syncthreads();
        cur ^= 1;
    }

    // partial store
    float* part = g_fc1part + (size_t)ks * BATCH * HID;
#pragma unroll
    for (int mf = 0; mf < 2; mf++) {
        int r0 = rowBase + wm * 32 + mf * 16 + lane / 4;
#pragma unroll
        for (int g2 = 0; g2 < 4; g2++)
#pragma unroll
            for (int jj = 0; jj < 2; jj++) {
                int n = wn * 64 + g2 * 16 + jj * 8 + (lane % 4) * 2;
                float* a = acc[mf][g2 * 2 + jj];
                part[(size_t)r0 * HID + n] = a[0];
                part[(size_t)r0 * HID + n + 1] = a[1];
                part[(size_t)(r0 + 8) * HID + n] = a[2];
                part[(size_t)(r0 + 8) * HID + n + 1] = a[3];
            }
    }
}

__global__ __launch_bounds__(256)
void fc1_reduce_kernel(const float* __restrict__ bl1) {
    int i4 = blockIdx.x * 256 + threadIdx.x;      // float4 index
    if (i4 >= BATCH * HID / 4) return;
    const float4* p = (const float4*)g_fc1part;
    const size_t S = (size_t)BATCH * HID / 4;
    float4 v0 = p[i4], v1 = p[i4 + S], v2 = p[i4 + 2 * S], v3 = p[i4 + 3 * S];
    float4 bb = *(const float4*)&bl1[(i4 & 31) * 4];
    float4 r;
    r.x = fmaxf(v0.x + v1.x + v2.x + v3.x + bb.x, 0.0f);
    r.y = fmaxf(v0.y + v1.y + v2.y + v3.y + bb.y, 0.0f);
    r.z = fmaxf(v0.z + v1.z + v2.z + v3.z + bb.z, 0.0f);
    r.w = fmaxf(v0.w + v1.w + v2.w + v3.w + bb.w, 0.0f);
    *(float4*)&g_h3[(size_t)i4 * 4] = r;
}

// ===========================================================================
// FC2 (128->10) + log_softmax.
// ===========================================================================
__global__ __launch_bounds__(256)
void fc2_kernel(const float* __restrict__ Wl2, const float* __restrict__ bl2,
                float* __restrict__ out, int B) {
    __shared__ float ws[128 * 10];
    __shared__ float bs[10];
    int tid = threadIdx.x;
    for (int i = tid; i < 1280; i += 256) ws[i] = Wl2[i];
    if (tid < 10) bs[tid] = bl2[tid];
    __syncthreads();

    int w = blockIdx.x * 8 + tid / 32;
    int lane = tid % 32;
    if (w >= B) return;

    const float* h = g_h3 + (size_t)w * HID;
    float acc[10];
#pragma unroll
    for (int j = 0; j < 10; j++) acc[j] = 0.0f;
#pragma unroll
    for (int i = 0; i < 4; i++) {
        int kk = lane + 32 * i;
        float hv = h[kk];
        const float* wr = &ws[kk * 10];
#pragma unroll
        for (int j = 0; j < 10; j++) acc[j] += hv * wr[j];
    }
#pragma unroll
    for (int j = 0; j < 10; j++)
#pragma unroll
        for (int off = 16; off > 0; off >>= 1)
            acc[j] += __shfl_xor_sync(0xffffffffu, acc[j], off);
    if (lane == 0) {
        float z[10];
        float mx = -1e30f;
#pragma unroll
        for (int j = 0; j < 10; j++) { z[j] = acc[j] + bs[j]; mx = fmaxf(mx, z[j]); }
        float s = 0.0f;
#pragma unroll
        for (int j = 0; j < 10; j++) s += expf(z[j] - mx);
        float l = logf(s);
#pragma unroll
        for (int j = 0; j < 10; j++) out[(size_t)w * 10 + j] = z[j] - mx - l;
    }
}

// ===========================================================================
extern "C" void kernel_launch(void* const* d_in, const int* in_sizes, int n_in,
                              void* d_out, int out_size) {
    const float* x   = (const float*)d_in[0];
    const float* W1  = (const float*)d_in[1];
    const float* b1  = (const float*)d_in[2];
    const float* W2  = (const float*)d_in[3];
    const float* b2  = (const float*)d_in[4];
    const float* Wl1 = (const float*)d_in[5];
    const float* bl1 = (const float*)d_in[6];
    const float* Wl2 = (const float*)d_in[7];
    const float* bl2 = (const float*)d_in[8];
    float* out = (float*)d_out;

    int B = in_sizes[0] / HW;   // 4096

    prep_w2_kernel<<<(64 * 296 + 255) / 256, 256>>>(W2);
    prep_wl1_kernel<<<(FEAT * 16 + 255) / 256, 256>>>(Wl1);

    cudaFuncSetAttribute(conv12_kernel,
                         cudaFuncAttributeMaxDynamicSharedMemorySize, C12_SMEM);
    conv12_kernel<<<B * 7, 224, C12_SMEM>>>(x, W1, b1, b2);

    cudaFuncSetAttribute(fc1_mma_kernel,
                         cudaFuncAttributeMaxDynamicSharedMemorySize, FC1_SMEM);
    fc1_mma_kernel<<<128, 256, FC1_SMEM>>>();
    fc1_reduce_kernel<<<(BATCH * HID / 4 + 255) / 256, 256>>>(bl1);

    fc2_kernel<<<(B + 7) / 8, 256>>>(Wl2, bl2, out, B);
}

// round 8
// speedup vs baseline: 7.4497x; 1.3247x over previous
#include <cuda_runtime.h>
#include <cuda_fp16.h>
#include <cstdint>

// ---------------------------------------------------------------------------
// Net_23905787969856 on GB300 (compute_103 => mma.sync fp16):
//  conv12: fused conv1 (SIMT, in smem) + conv2 (mma.sync fp16) with
//          window-permuted M-tiles (4x4 pixel blocks) -> in-register 2x2
//          maxpool via shfl -> h2 fp16 NHWC-pooled directly to gmem.
//          2 m-tiles per B-fragment load to cut LDSM traffic.
//  fc1:    mma.sync fp16 (A single plane), M128/N128, split-K=8, cp.async
//          double buffered -> fp32 partials -> reduce+bias+relu
//  fc2:    fp32 + log_softmax
// ---------------------------------------------------------------------------

#define BATCH 4096
#define HW 784
#define POOLHW 196
#define FEAT 12544
#define HID 128

__device__ __half g_h2[(size_t)BATCH * FEAT];     // [B][pos][co] NHWC-pooled
__device__ __half g_w2[64 * 296];                 // [co][t*32+ci] im2col fp16
__device__ __half g_wl1[(size_t)HID * FEAT];      // [n][k] permuted fp16
__device__ float g_fc1part[(size_t)8 * BATCH * HID];
__device__ float g_h3[(size_t)BATCH * HID];

__device__ __forceinline__ uint32_t smem_u32(const void* p) {
    uint32_t a;
    asm("{ .reg .u64 t; cvta.to.shared.u64 t, %1; cvt.u32.u64 %0, t; }"
        : "=r"(a) : "l"(p));
    return a;
}
__device__ __forceinline__ void ldm_x4(uint32_t addr, uint32_t& r0, uint32_t& r1,
                                       uint32_t& r2, uint32_t& r3) {
    asm volatile("ldmatrix.sync.aligned.m8n8.x4.shared.b16 {%0,%1,%2,%3}, [%4];"
                 : "=r"(r0), "=r"(r1), "=r"(r2), "=r"(r3) : "r"(addr));
}
__device__ __forceinline__ void mma_f16(float* c, uint32_t a0, uint32_t a1,
                                        uint32_t a2, uint32_t a3,
                                        uint32_t b0, uint32_t b1) {
    asm volatile(
        "mma.sync.aligned.m16n8k16.row.col.f32.f16.f16.f32 "
        "{%0,%1,%2,%3}, {%4,%5,%6,%7}, {%8,%9}, {%0,%1,%2,%3};"
        : "+f"(c[0]), "+f"(c[1]), "+f"(c[2]), "+f"(c[3])
        : "r"(a0), "r"(a1), "r"(a2), "r"(a3), "r"(b0), "r"(b1));
}
#define CP_ASYNC16(dst, src) \
    asm volatile("cp.async.cg.shared.global [%0], [%1], 16;" :: "r"(dst), "l"(src))
#define CP_COMMIT() asm volatile("cp.async.commit_group;" ::: "memory")
#define CP_WAIT0()  asm volatile("cp.async.wait_group 0;" ::: "memory")

// ===========================================================================
// Prep kernels
// ===========================================================================
__global__ void prep_w2_kernel(const float* __restrict__ W2) {
    int i = blockIdx.x * 256 + threadIdx.x;
    if (i >= 64 * 296) return;
    int co = i / 296, col = i % 296;
    float w = 0.0f;
    if (col < 288) {
        int t = col / 32, ci = col % 32;
        w = W2[co * 288 + ci * 9 + t];
    }
    g_w2[i] = __float2half_rn(w);
}

// Coalesced transpose+permute: one CTA per pooled position (196 CTAs).
// g_wl1[n][pos*64+co] = Wl1[co*196+pos][n]
__global__ __launch_bounds__(256)
void prep_wl1_kernel(const float* __restrict__ Wl1) {
    __shared__ float smw[64 * 129];
    int pos = blockIdx.x;
    int tid = threadIdx.x;
    for (int i = tid; i < 64 * 128; i += 256) {
        int co = i >> 7, n = i & 127;
        smw[co * 129 + n] = Wl1[(size_t)(co * POOLHW + pos) * HID + n];
    }
    __syncthreads();
    for (int i = tid; i < 128 * 64; i += 256) {
        int n = i >> 6, co = i & 63;
        g_wl1[(size_t)n * FEAT + pos * 64 + co] = __float2half_rn(smw[co * 129 + n]);
    }
}

// ===========================================================================
// conv12: CTA = (image, h) ; h=0: image rows 0-15 (28 tiles), h=1: rows 16-27
// (21 tiles). M-tile = 2x2 window block (4x4 pixels, 16 rows in window-perm
// order). 8 warps, 2 tiles per pass, n=64 per warp.
// ===========================================================================
#define OFF_A 0                          // 18 rows * 30 px * 80B = 43200
#define OFF_B 43200                      // 64 * 592 = 37888
#define OFF_XS 81088                     // 20*32*4 = 2560
#define OFF_W1 83648                     // 288*4
#define OFF_B1 84800                     // 32*4
#define OFF_B2 84928                     // 64*4
#define C12_SMEM 85184
#define BROW 592

__global__ __launch_bounds__(256, 2)
void conv12_kernel(const float* __restrict__ x,
                   const float* __restrict__ W1, const float* __restrict__ b1,
                   const float* __restrict__ b2) {
    extern __shared__ char sm[];
    uint32_t smb = smem_u32(sm);
    float* xs  = (float*)(sm + OFF_XS);     // [20][32]
    float* w1s = (float*)(sm + OFF_W1);
    float* b1s = (float*)(sm + OFF_B1);
    float* b2s = (float*)(sm + OFF_B2);
    int tid = threadIdx.x, wid = tid >> 5, lane = tid & 31;
    int b = blockIdx.x >> 1, h = blockIdx.x & 1;
    int base_ir = h * 16;
    int T = h ? 21 : 28;                    // m-tiles this CTA

    // ---- B via cp.async (overlaps conv1)
    for (int i = tid; i < 2368; i += 256)
        CP_ASYNC16(smb + OFF_B + i * 16, (const char*)g_w2 + i * 16);
    CP_COMMIT();

    // ---- xs slab: image rows [base_ir-2 .. base_ir+17], cols [-2..29]
    for (int i = tid; i < 640; i += 256) {
        int r = i >> 5, c = i & 31;
        int ir = base_ir + r - 2, ic = c - 2;
        float v = 0.0f;
        if (ir >= 0 && ir < 28 && ic >= 0 && ic < 28)
            v = x[(size_t)b * HW + ir * 28 + ic];
        xs[i] = v;
    }
    for (int i = tid; i < 288; i += 256) w1s[i] = W1[i];
    if (tid < 32) b1s[tid] = b1[tid];
    if (tid < 64) b2s[tid] = b2[tid];
    __syncthreads();

    // ---- conv1 -> A plane: 18 rows x 30 cols x 32 ch fp16, pixel stride 80B
    {
        int c = tid & 31;
        float w1r[9];
#pragma unroll
        for (int k = 0; k < 9; k++) w1r[k] = w1s[c * 9 + k];
        float b1r = b1s[c];
        for (int i = tid; i < 18 * 30 * 32; i += 256) {
            int lin = i >> 5;             // channel c constant per thread
            int ac = lin % 30, ar = lin / 30;
            int ir = base_ir + ar - 1, ic = ac - 1;
            float val = 0.0f;
            if (ir >= 0 && ir < 28 && ic >= 0 && ic < 28) {
                float cen = xs[(ar + 1) * 32 + ac + 1];
                float acc = b1r;
#pragma unroll
                for (int ky = 0; ky < 3; ky++)
#pragma unroll
                    for (int kx = 0; kx < 3; kx++)
                        acc = fmaf(w1r[ky * 3 + kx], xs[(ar + ky) * 32 + ac + kx], acc);
                val = (cen != 0.0f) ? fmaxf(acc, 0.0f) : 0.0f;
            }
            *(__half*)(sm + OFF_A + lin * 80 + c * 2) = __float2half_rn(val);
        }
    }
    CP_WAIT0();
    __syncthreads();

    uint32_t bBase = smb + OFF_B + (uint32_t)(lane & 15) * BROW + ((lane >> 4) << 4);
    int rA = lane >> 2;                    // 0..7 : a0/a1 row; a2/a3 = rA+8
    int jm = rA & 3;                       // window member
    int widxA = rA >> 2;                   // 0/1 -> wr offset

    for (int p = 0; p < 2; p++) {
        int t0 = p * 16 + wid * 2;
        int nt = T - t0; nt = nt > 2 ? 2 : nt;
        if (nt <= 0) continue;

        float acc[2][8][4];
#pragma unroll
        for (int u = 0; u < 2; u++)
#pragma unroll
            for (int g = 0; g < 8; g++)
#pragma unroll
                for (int q = 0; q < 4; q++) acc[u][g][q] = 0.0f;

        uint32_t apix[2];
        int brc[2], bcc[2];
#pragma unroll
        for (int u = 0; u < 2; u++) {
            int t = t0 + ((u < nt) ? u : 0);
            int br = t / 7, bc = t % 7;
            brc[u] = br; bcc[u] = bc;
            int r = lane & 15;
            int j = r & 3, widx = r >> 2;
            int wr = 2 * br + (widx & 1), wc = 2 * bc + (widx >> 1);
            // A base = top-left tap of the 3x3 window for output pixel
            // (2wr + (j>>1), 2wc + (j&1)): A row = output row (image row -1
            // maps to A row +1 and tap dy starts at 0) -- NO +1 here.
            int ar = 2 * wr + (j >> 1), ac = 2 * wc + (j & 1);
            apix[u] = smb + OFF_A + (uint32_t)(ar * 30 + ac) * 80 + ((lane >> 4) << 4);
        }

#pragma unroll
        for (int s = 0; s < 18; s++) {
            const int t9 = s >> 1;
            const uint32_t aoff = (uint32_t)(((t9 / 3) * 30 + (t9 % 3)) * 80 + (s & 1) * 32);
            const uint32_t kb = (uint32_t)s * 32;
            uint32_t a00, a01, a02, a03, a10, a11, a12, a13;
            ldm_x4(apix[0] + aoff, a00, a01, a02, a03);
            ldm_x4(apix[1] + aoff, a10, a11, a12, a13);
#pragma unroll
            for (int g2 = 0; g2 < 4; g2++) {
                uint32_t f0, f1, f2, f3;
                ldm_x4(bBase + (uint32_t)g2 * (16 * BROW) + kb, f0, f1, f2, f3);
                mma_f16(acc[0][2 * g2],     a00, a01, a02, a03, f0, f2);
                mma_f16(acc[0][2 * g2 + 1], a00, a01, a02, a03, f1, f3);
                mma_f16(acc[1][2 * g2],     a10, a11, a12, a13, f0, f2);
                mma_f16(acc[1][2 * g2 + 1], a10, a11, a12, a13, f1, f3);
            }
        }

        // ---- epilogue: bias + mask + relu, shfl-pool, store pooled h2
        for (int u = 0; u < nt; u++) {
            int br = brc[u], bc = bcc[u];
            int wrA = 2 * br + widxA;
            int wcA = 2 * bc;
            int xsr = 2 * wrA + (jm >> 1) + 2;
            int xcA = 2 * wcA + (jm & 1) + 2;
            bool mA = xs[xsr * 32 + xcA] != 0.0f;         // window (wrA, wcA)
            bool mB = xs[xsr * 32 + xcA + 2] != 0.0f;     // window (wrA, wcA+1)
            int posA = (h * 8 + wrA) * 14 + wcA;
            size_t obase = (size_t)b * FEAT;
#pragma unroll
            for (int g = 0; g < 8; g++) {
                int c0 = g * 8 + (lane & 3) * 2;
                float bb0 = b2s[c0], bb1 = b2s[c0 + 1];
                float v0 = mA ? fmaxf(acc[u][g][0] + bb0, 0.0f) : 0.0f;
                float v1 = mA ? fmaxf(acc[u][g][1] + bb1, 0.0f) : 0.0f;
                float v2 = mB ? fmaxf(acc[u][g][2] + bb0, 0.0f) : 0.0f;
                float v3 = mB ? fmaxf(acc[u][g][3] + bb1, 0.0f) : 0.0f;
                v0 = fmaxf(v0, __shfl_xor_sync(~0u, v0, 4));
                v0 = fmaxf(v0, __shfl_xor_sync(~0u, v0, 8));
                v1 = fmaxf(v1, __shfl_xor_sync(~0u, v1, 4));
                v1 = fmaxf(v1, __shfl_xor_sync(~0u, v1, 8));
                v2 = fmaxf(v2, __shfl_xor_sync(~0u, v2, 4));
                v2 = fmaxf(v2, __shfl_xor_sync(~0u, v2, 8));
                v3 = fmaxf(v3, __shfl_xor_sync(~0u, v3, 4));
                v3 = fmaxf(v3, __shfl_xor_sync(~0u, v3, 8));
                if (jm == 0) {
                    __half2 h01 = __halves2half2(__float2half_rn(v0), __float2half_rn(v1));
                    __half2 h23 = __halves2half2(__float2half_rn(v2), __float2half_rn(v3));
                    *(__half2*)&g_h2[obase + (size_t)posA * 64 + c0] = h01;
                    *(__half2*)&g_h2[obase + (size_t)(posA + 1) * 64 + c0] = h23;
                }
            }
        }
    }
}

// ===========================================================================
// FC1: M=128,N=128 tile, split-K=8 (chunk 1568), 8 warps, cp.async 2-stage.
// A single fp16 plane x B fp16. Partials to g_fc1part.
// ===========================================================================
#define FC1_RS 40
#define FC1_PLANE (128 * FC1_RS * 2)     // 10240
#define FC1_STAGE (2 * FC1_PLANE)        // A, B
#define FC1_SMEM (2 * FC1_STAGE)         // 40960

__global__ __launch_bounds__(256, 2)
void fc1_mma_kernel(int mtiles) {
    extern __shared__ char sm[];
    uint32_t smb = smem_u32(sm);
    int tid = threadIdx.x;
    int wid = tid >> 5, lane = tid & 31;
    int mtile = blockIdx.x % mtiles;
    int ks = blockIdx.x / mtiles;        // 0..7
    int rowBase = mtile * 128;
    int kbase = ks * 1568;

    float acc[2][8][4];
#pragma unroll
    for (int mf = 0; mf < 2; mf++)
#pragma unroll
        for (int n = 0; n < 8; n++)
#pragma unroll
            for (int j = 0; j < 4; j++) acc[mf][n][j] = 0.0f;

    auto load_stage = [&](int stg, int kpos) {
        uint32_t base = smb + stg * FC1_STAGE;
#pragma unroll
        for (int j = 0; j < 4; j++) {
            int i = tid + j * 256;       // 0..1023: <512 A, else B
            int ii = i & 511;
            int row = ii >> 2, q = ii & 3;
            uint32_t dst = base + (i < 512 ? 0 : FC1_PLANE)
                         + (uint32_t)(row * FC1_RS + q * 8) * 2;
            const __half* src = (i < 512)
                ? &g_h2[(size_t)(rowBase + row) * FEAT + kpos + q * 8]
                : &g_wl1[(size_t)row * FEAT + kpos + q * 8];
            CP_ASYNC16(dst, src);
        }
    };

    int wm = wid >> 1, wn = wid & 1;
    uint32_t aOff = (uint32_t)((wm * 32 + (lane & 15)) * FC1_RS + (lane >> 4) * 8) * 2;
    uint32_t bOff = (uint32_t)((wn * 64 + (lane & 15)) * FC1_RS + (lane >> 4) * 8) * 2
                    + FC1_PLANE;

    load_stage(0, kbase);
    CP_COMMIT();

    int cur = 0;
    for (int it = 0; it < 49; it++) {
        CP_WAIT0();
        __syncthreads();
        if (it + 1 < 49) {
            load_stage(cur ^ 1, kbase + (it + 1) * 32);
            CP_COMMIT();
        }
        uint32_t stg = smb + cur * FC1_STAGE;
#pragma unroll
        for (int kk = 0; kk < 2; kk++) {
            uint32_t kb = (uint32_t)kk * 32;
            uint32_t bfr[16];
#pragma unroll
            for (int g2 = 0; g2 < 4; g2++)
                ldm_x4(stg + bOff + (uint32_t)(g2 * 16 * FC1_RS) * 2 + kb,
                       bfr[g2 * 4], bfr[g2 * 4 + 1], bfr[g2 * 4 + 2], bfr[g2 * 4 + 3]);
#pragma unroll
            for (int mf = 0; mf < 2; mf++) {
                uint32_t a0, a1, a2, a3;
                ldm_x4(stg + aOff + (uint32_t)(mf * 16 * FC1_RS) * 2 + kb, a0, a1, a2, a3);
#pragma unroll
                for (int g2 = 0; g2 < 4; g2++) {
                    mma_f16(acc[mf][g2 * 2],     a0, a1, a2, a3, bfr[g2 * 4],     bfr[g2 * 4 + 2]);
                    mma_f16(acc[mf][g2 * 2 + 1], a0, a1, a2, a3, bfr[g2 * 4 + 1], bfr[g2 * 4 + 3]);
                }
            }
        }
        __syncthreads();
        cur ^= 1;
    }

    float* part = g_fc1part + (size_t)ks * BATCH * HID;
#pragma unroll
    for (int mf = 0; mf < 2; mf++) {
        int r0 = rowBase + wm * 32 + mf * 16 + lane / 4;
#pragma unroll
        for (int g2 = 0; g2 < 4; g2++)
#pragma unroll
            for (int jj = 0; jj < 2; jj++) {
                int n = wn * 64 + g2 * 16 + jj * 8 + (lane % 4) * 2;
                float* a = acc[mf][g2 * 2 + jj];
                part[(size_t)r0 * HID + n] = a[0];
                part[(size_t)r0 * HID + n + 1] = a[1];
                part[(size_t)(r0 + 8) * HID + n] = a[2];
                part[(size_t)(r0 + 8) * HID + n + 1] = a[3];
            }
    }
}

__global__ __launch_bounds__(256)
void fc1_reduce_kernel(const float* __restrict__ bl1, int total4) {
    int i4 = blockIdx.x * 256 + threadIdx.x;
    if (i4 >= total4) return;
    const float4* p = (const float4*)g_fc1part;
    const size_t S = (size_t)BATCH * HID / 4;
    float4 s = p[i4];
#pragma unroll
    for (int k = 1; k < 8; k++) {
        float4 v = p[i4 + (size_t)k * S];
        s.x += v.x; s.y += v.y; s.z += v.z; s.w += v.w;
    }
    float4 bb = *(const float4*)&bl1[(i4 & 31) * 4];
    float4 r;
    r.x = fmaxf(s.x + bb.x, 0.0f);
    r.y = fmaxf(s.y + bb.y, 0.0f);
    r.z = fmaxf(s.z + bb.z, 0.0f);
    r.w = fmaxf(s.w + bb.w, 0.0f);
    *(float4*)&g_h3[(size_t)i4 * 4] = r;
}

// ===========================================================================
// FC2 (128->10) + log_softmax.
// ===========================================================================
__global__ __launch_bounds__(256)
void fc2_kernel(const float* __restrict__ Wl2, const float* __restrict__ bl2,
                float* __restrict__ out, int B) {
    __shared__ float ws[128 * 10];
    __shared__ float bs[10];
    int tid = threadIdx.x;
    for (int i = tid; i < 1280; i += 256) ws[i] = Wl2[i];
    if (tid < 10) bs[tid] = bl2[tid];
    __syncthreads();

    int w = blockIdx.x * 8 + tid / 32;
    int lane = tid % 32;
    if (w >= B) return;

    const float* hh = g_h3 + (size_t)w * HID;
    float acc[10];
#pragma unroll
    for (int j = 0; j < 10; j++) acc[j] = 0.0f;
#pragma unroll
    for (int i = 0; i < 4; i++) {
        int kk = lane + 32 * i;
        float hv = hh[kk];
        const float* wr = &ws[kk * 10];
#pragma unroll
        for (int j = 0; j < 10; j++) acc[j] += hv * wr[j];
    }
#pragma unroll
    for (int j = 0; j < 10; j++)
#pragma unroll
        for (int off = 16; off > 0; off >>= 1)
            acc[j] += __shfl_xor_sync(0xffffffffu, acc[j], off);
    if (lane == 0) {
        float z[10];
        float mx = -1e30f;
#pragma unroll
        for (int j = 0; j < 10; j++) { z[j] = acc[j] + bs[j]; mx = fmaxf(mx, z[j]); }
        float s = 0.0f;
#pragma unroll
        for (int j = 0; j < 10; j++) s += expf(z[j] - mx);
        float l = logf(s);
#pragma unroll
        for (int j = 0; j < 10; j++) out[(size_t)w * 10 + j] = z[j] - mx - l;
    }
}

// ===========================================================================
extern "C" void kernel_launch(void* const* d_in, const int* in_sizes, int n_in,
                              void* d_out, int out_size) {
    const float* x   = (const float*)d_in[0];
    const float* W1  = (const float*)d_in[1];
    const float* b1  = (const float*)d_in[2];
    const float* W2  = (const float*)d_in[3];
    const float* b2  = (const float*)d_in[4];
    const float* Wl1 = (const float*)d_in[5];
    const float* bl1 = (const float*)d_in[6];
    const float* Wl2 = (const float*)d_in[7];
    const float* bl2 = (const float*)d_in[8];
    float* out = (float*)d_out;

    int B = in_sizes[0] / HW;   // 4096

    prep_w2_kernel<<<(64 * 296 + 255) / 256, 256>>>(W2);
    prep_wl1_kernel<<<POOLHW, 256>>>(Wl1);

    cudaFuncSetAttribute(conv12_kernel,
                         cudaFuncAttributeMaxDynamicSharedMemorySize, C12_SMEM);
    conv12_kernel<<<B * 2, 256, C12_SMEM>>>(x, W1, b1, b2);

    int mtiles = B / 128;
    cudaFuncSetAttribute(fc1_mma_kernel,
                         cudaFuncAttributeMaxDynamicSharedMemorySize, FC1_SMEM);
    fc1_mma_kernel<<<mtiles * 8, 256, FC1_SMEM>>>(mtiles);

    int total4 = B * HID / 4;
    fc1_reduce_kernel<<<(total4 + 255) / 256, 256>>>(bl1, total4);

    fc2_kernel<<<(B + 7) / 8, 256>>>(Wl2, bl2, out, B);
}